// round 3
// baseline (speedup 1.0000x reference)
#include <cuda_runtime.h>

// Problem constants (from reference): B=4096, D=512, K=10, L=256, V=80
#define BQ 4096
#define DD 512
#define KK 10
#define LL 256
#define VV 80

// Scratch for alpha[0:10], beta[10:20], kappa[20:30] per batch row.
__device__ float g_abk[BQ * 30];

// exp(e) for e in [-50, 0], FMA-pipe only (no MUFU).
// exp(e) = 2^(e*log2e) = 2^i * 2^f, i=floor(t), f in [0,1), deg-6 Taylor (err ~2e-6 rel).
__device__ __forceinline__ float fast_exp_neg(float e) {
    float t = e * 1.44269504088896341f;
    int i = __float2int_rd(t);            // t in [-72.14, 0] -> i in [-73, 0]
    float f = t - (float)i;
    float p = 1.5403530393381610e-4f;
    p = fmaf(p, f, 1.3333558146428443e-3f);
    p = fmaf(p, f, 9.6181291076284772e-3f);
    p = fmaf(p, f, 5.5504108664821580e-2f);
    p = fmaf(p, f, 2.4022650695910071e-1f);
    p = fmaf(p, f, 6.9314718055994531e-1f);
    p = fmaf(p, f, 1.0f);
    return p * __int_as_float((i + 127) << 23);
}

// Kernel A: raw = X@W + b, activations, write kappa to output + abk scratch.
// 128 blocks x 256 threads, each block does 32 batch rows.
// Warp layout: warp w owns rows 4w..4w+3, lane = output column (lanes 30,31 idle at write).
__global__ __launch_bounds__(256) void gemm_act_kernel(
    const float* __restrict__ X, const float* __restrict__ W,
    const float* __restrict__ bias, const float* __restrict__ prev_kappa,
    const float* __restrict__ kappa_scale_p, float* __restrict__ out_kappa)
{
    __shared__ float Xs[32][128];
    __shared__ float Wsh[128 * 30 + 32];   // +32 pad: lanes 30/31 read harmlessly
    const int tid  = threadIdx.x;
    const int warp = tid >> 5;
    const int lane = tid & 31;
    const int b0   = blockIdx.x * 32;

    float acc[4] = {0.f, 0.f, 0.f, 0.f};

    for (int dt = 0; dt < DD; dt += 128) {
        __syncthreads();
        // W slab [dt:dt+128, 0:30] is contiguous in row-major W.
        for (int i = tid; i < 128 * 30; i += 256) Wsh[i] = W[dt * 30 + i];
        for (int i = tid; i < 32 * 128; i += 256) {
            int r = i >> 7, c = i & 127;
            Xs[r][c] = X[(size_t)(b0 + r) * DD + dt + c];
        }
        __syncthreads();
        #pragma unroll 4
        for (int d = 0; d < 128; ++d) {
            float wv = Wsh[d * 30 + lane];
            acc[0] = fmaf(Xs[warp * 4 + 0][d], wv, acc[0]);
            acc[1] = fmaf(Xs[warp * 4 + 1][d], wv, acc[1]);
            acc[2] = fmaf(Xs[warp * 4 + 2][d], wv, acc[2]);
            acc[3] = fmaf(Xs[warp * 4 + 3][d], wv, acc[3]);
        }
    }

    if (lane < 30) {
        const float bj = bias[lane];
        const float ks = *kappa_scale_p;
        #pragma unroll
        for (int rr = 0; rr < 4; ++rr) {
            int b = b0 + warp * 4 + rr;
            float raw = acc[rr] + bj;
            float val;
            if (lane < 20) {
                // alpha (lane<10) or beta (10<=lane<20): exp(clip(raw,-8,8))
                val = __expf(fminf(fmaxf(raw, -8.f), 8.f));
            } else {
                float dk = __expf(fminf(fmaxf(raw + ks, -8.f), 5.f));
                val = prev_kappa[b * KK + (lane - 20)] + dk;
                out_kappa[b * KK + (lane - 20)] = val;
            }
            g_abk[b * 30 + lane] = val;
        }
    }
}

// Kernel B: per batch row, compute phi[l] (l<seqlen) then w[v] = sum_l phi[l]*oh[b,l,v].
// 4096 blocks x 320 threads. 4 groups of 80 threads (thread<->v), stride-4 over l,
// manual unroll-4 => 16 coalesced 320B row reads in flight per block.
__global__ __launch_bounds__(320) void phi_w_kernel(
    const float* __restrict__ oh, const int* __restrict__ seqlens,
    float* __restrict__ out_w)
{
    __shared__ float s_abk[30];
    __shared__ float s_phi[LL];
    __shared__ float s_red[320];
    const int b   = blockIdx.x;
    const int tid = threadIdx.x;

    if (tid < 30) s_abk[tid] = g_abk[b * 30 + tid];
    __syncthreads();

    const int seqlen = seqlens[b];

    if (tid < LL && tid < seqlen) {
        float u = (float)(tid + 1);
        float s = 0.f;
        #pragma unroll
        for (int k = 0; k < KK; ++k) {
            float al = s_abk[k];
            float be = s_abk[10 + k];
            float ka = s_abk[20 + k];
            float dv = ka - u;
            float e  = fmaxf(-be * dv * dv, -50.f);   // exponent always <= 0
            s = fmaf(al, fast_exp_neg(e), s);
        }
        s_phi[tid] = s;
    }
    __syncthreads();

    const int g = tid / VV;          // group 0..3
    const int v = tid - g * VV;      // 0..79
    const float* row = oh + (size_t)b * (LL * VV) + v;

    float a0 = 0.f, a1 = 0.f, a2 = 0.f, a3 = 0.f;
    int l = g;
    for (; l + 12 < seqlen; l += 16) {
        a0 = fmaf(s_phi[l],      row[(size_t)(l)      * VV], a0);
        a1 = fmaf(s_phi[l + 4],  row[(size_t)(l + 4)  * VV], a1);
        a2 = fmaf(s_phi[l + 8],  row[(size_t)(l + 8)  * VV], a2);
        a3 = fmaf(s_phi[l + 12], row[(size_t)(l + 12) * VV], a3);
    }
    for (; l < seqlen; l += 4)
        a0 = fmaf(s_phi[l], row[(size_t)l * VV], a0);

    s_red[tid] = (a0 + a1) + (a2 + a3);
    __syncthreads();
    if (tid < VV)
        out_w[b * VV + tid] = (s_red[tid] + s_red[tid + 80]) +
                              (s_red[tid + 160] + s_red[tid + 240]);
}

extern "C" void kernel_launch(void* const* d_in, const int* in_sizes, int n_in,
                              void* d_out, int out_size) {
    const float* X          = (const float*)d_in[0];   // [B, D]
    const float* prev_kappa = (const float*)d_in[1];   // [B, K]
    const float* oh         = (const float*)d_in[2];   // [B, L, V]
    const int*   seqlens    = (const int*)  d_in[3];   // [B]
    const float* W          = (const float*)d_in[4];   // [D, 3K]
    const float* bias       = (const float*)d_in[5];   // [3K]
    const float* ks         = (const float*)d_in[6];   // scalar

    float* out       = (float*)d_out;
    float* out_w     = out;              // [B, V] first (reference returns (w, kappa))
    float* out_kappa = out + BQ * VV;    // [B, K] second

    gemm_act_kernel<<<128, 256>>>(X, W, bias, prev_kappa, ks, out_kappa);
    phi_w_kernel<<<BQ, 320>>>(oh, seqlens, out_w);
}

// round 4
// speedup vs baseline: 1.1574x; 1.1574x over previous
#include <cuda_runtime.h>

// Problem constants (from reference): B=4096, D=512, K=10, L=256, V=80
#define BQ 4096
#define DD 512
#define KK 10
#define LL 256
#define VV 80

// Scratch for alpha[0:10], beta[10:20], kappa[20:30] per batch row.
__device__ float g_abk[BQ * 30];

// exp(e) for e in [-50, 0], FMA-pipe only (no MUFU).
// exp(e) = 2^(e*log2e) = 2^i * 2^f, i=floor(t), f in [0,1), deg-6 Taylor (err ~2e-6 rel).
__device__ __forceinline__ float fast_exp_neg(float e) {
    float t = e * 1.44269504088896341f;
    int i = __float2int_rd(t);            // t in [-72.14, 0] -> i in [-73, 0]
    float f = t - (float)i;
    float p = 1.5403530393381610e-4f;
    p = fmaf(p, f, 1.3333558146428443e-3f);
    p = fmaf(p, f, 9.6181291076284772e-3f);
    p = fmaf(p, f, 5.5504108664821580e-2f);
    p = fmaf(p, f, 2.4022650695910071e-1f);
    p = fmaf(p, f, 6.9314718055994531e-1f);
    p = fmaf(p, f, 1.0f);
    return p * __int_as_float((i + 127) << 23);
}

// Kernel A: raw = X@W + b, activations, write kappa to output + abk scratch.
// 128 blocks x 256 threads; block = 32 batch rows; warp w owns rows 4w..4w+3,
// lane = output column (lanes 30,31 idle). X staged as float4 in shared so the
// inner loop is 4 broadcast LDS.128 + 4 LDS.32 + 16 FMA per 4-d chunk.
__global__ __launch_bounds__(256) void gemm_act_kernel(
    const float* __restrict__ X, const float* __restrict__ W,
    const float* __restrict__ bias, const float* __restrict__ prev_kappa,
    const float* __restrict__ kappa_scale_p, float* __restrict__ out_kappa)
{
    __shared__ float4 Xs4[32 * 32];                 // 32 rows x 32 float4 (128 d) = 16 KB
    __shared__ __align__(16) float Wsh[128 * 30 + 4]; // W tile + pad for lanes 30/31

    const int tid  = threadIdx.x;
    const int warp = tid >> 5;
    const int lane = tid & 31;
    const int b0   = blockIdx.x * 32;

    const float4* X4 = (const float4*)X;
    const float4* W4 = (const float4*)W;   // W is [512,30] row-major -> 3840 float4 linear

    float acc[4] = {0.f, 0.f, 0.f, 0.f};

    for (int t = 0; t < 4; ++t) {
        __syncthreads();
        // W tile: floats [t*3840, t*3840+3840) == float4 [t*960, +960)
        for (int i = tid; i < 960; i += 256)
            ((float4*)Wsh)[i] = W4[t * 960 + i];
        // X tile: 32 rows x 32 float4 (d = t*128 .. t*128+127), coalesced
        for (int i = tid; i < 1024; i += 256) {
            int r = i >> 5, c = i & 31;
            Xs4[i] = X4[(size_t)(b0 + r) * 128 + t * 32 + c];
        }
        __syncthreads();

        const float4* xr0 = &Xs4[(warp * 4 + 0) * 32];
        const float4* xr1 = &Xs4[(warp * 4 + 1) * 32];
        const float4* xr2 = &Xs4[(warp * 4 + 2) * 32];
        const float4* xr3 = &Xs4[(warp * 4 + 3) * 32];

        #pragma unroll 4
        for (int c = 0; c < 32; ++c) {
            float w0 = Wsh[(4 * c + 0) * 30 + lane];
            float w1 = Wsh[(4 * c + 1) * 30 + lane];
            float w2 = Wsh[(4 * c + 2) * 30 + lane];
            float w3 = Wsh[(4 * c + 3) * 30 + lane];
            float4 x0 = xr0[c], x1 = xr1[c], x2 = xr2[c], x3 = xr3[c];
            acc[0] = fmaf(x0.x, w0, fmaf(x0.y, w1, fmaf(x0.z, w2, fmaf(x0.w, w3, acc[0]))));
            acc[1] = fmaf(x1.x, w0, fmaf(x1.y, w1, fmaf(x1.z, w2, fmaf(x1.w, w3, acc[1]))));
            acc[2] = fmaf(x2.x, w0, fmaf(x2.y, w1, fmaf(x2.z, w2, fmaf(x2.w, w3, acc[2]))));
            acc[3] = fmaf(x3.x, w0, fmaf(x3.y, w1, fmaf(x3.z, w2, fmaf(x3.w, w3, acc[3]))));
        }
    }

    if (lane < 30) {
        const float bj = bias[lane];
        const float ks = *kappa_scale_p;
        #pragma unroll
        for (int rr = 0; rr < 4; ++rr) {
            int b = b0 + warp * 4 + rr;
            float raw = acc[rr] + bj;
            float val;
            if (lane < 20) {
                // alpha (lane<10) or beta (10<=lane<20): exp(clip(raw,-8,8))
                val = __expf(fminf(fmaxf(raw, -8.f), 8.f));
            } else {
                float dk = __expf(fminf(fmaxf(raw + ks, -8.f), 5.f));
                val = prev_kappa[b * KK + (lane - 20)] + dk;
                out_kappa[b * KK + (lane - 20)] = val;
            }
            g_abk[b * 30 + lane] = val;
        }
    }
}

// Kernel B: per batch row, compute phi[l] (l<seqlen) then w[v] = sum_l phi[l]*oh[b,l,v].
// 4096 blocks x 320 threads. V=80 floats = 20 float4 per row; 16 l-groups x 20
// float4-lanes. Rows are contiguous at 320B so the whole block reads contiguous
// memory. Unroll-4 LDG.128 per thread -> ~2KB/warp in flight (MLP fix).
__global__ __launch_bounds__(320) void phi_w_kernel(
    const float* __restrict__ oh, const int* __restrict__ seqlens,
    float* __restrict__ out_w)
{
    __shared__ float  s_abk[30];
    __shared__ float  s_phi[LL];
    __shared__ float4 s_red[320];
    __shared__ float4 s_red2[80];
    const int b   = blockIdx.x;
    const int tid = threadIdx.x;

    if (tid < 30) s_abk[tid] = g_abk[b * 30 + tid];
    __syncthreads();

    const int seqlen = seqlens[b];

    if (tid < LL && tid < seqlen) {
        float u = (float)(tid + 1);
        float s = 0.f;
        #pragma unroll
        for (int k = 0; k < KK; ++k) {
            float al = s_abk[k];
            float be = s_abk[10 + k];
            float ka = s_abk[20 + k];
            float dv = ka - u;
            float e  = fmaxf(-be * dv * dv, -50.f);   // exponent always <= 0
            s = fmaf(al, fast_exp_neg(e), s);
        }
        s_phi[tid] = s;
    }
    __syncthreads();

    const int g  = tid / 20;         // l-group 0..15
    const int v4 = tid - g * 20;     // float4 lane 0..19
    const float4* row = (const float4*)oh + (size_t)b * (LL * VV / 4) + v4;

    float4 a0 = make_float4(0.f, 0.f, 0.f, 0.f);
    float4 a1 = a0;
    int l = g;
    for (; l + 48 < seqlen; l += 64) {
        float4 x0 = row[(size_t)(l)      * 20];
        float4 x1 = row[(size_t)(l + 16) * 20];
        float4 x2 = row[(size_t)(l + 32) * 20];
        float4 x3 = row[(size_t)(l + 48) * 20];
        float p0 = s_phi[l], p1 = s_phi[l + 16], p2 = s_phi[l + 32], p3 = s_phi[l + 48];
        a0.x = fmaf(p0, x0.x, a0.x); a0.y = fmaf(p0, x0.y, a0.y);
        a0.z = fmaf(p0, x0.z, a0.z); a0.w = fmaf(p0, x0.w, a0.w);
        a1.x = fmaf(p1, x1.x, a1.x); a1.y = fmaf(p1, x1.y, a1.y);
        a1.z = fmaf(p1, x1.z, a1.z); a1.w = fmaf(p1, x1.w, a1.w);
        a0.x = fmaf(p2, x2.x, a0.x); a0.y = fmaf(p2, x2.y, a0.y);
        a0.z = fmaf(p2, x2.z, a0.z); a0.w = fmaf(p2, x2.w, a0.w);
        a1.x = fmaf(p3, x3.x, a1.x); a1.y = fmaf(p3, x3.y, a1.y);
        a1.z = fmaf(p3, x3.z, a1.z); a1.w = fmaf(p3, x3.w, a1.w);
    }
    for (; l < seqlen; l += 16) {
        float4 x = row[(size_t)l * 20];
        float p = s_phi[l];
        a0.x = fmaf(p, x.x, a0.x); a0.y = fmaf(p, x.y, a0.y);
        a0.z = fmaf(p, x.z, a0.z); a0.w = fmaf(p, x.w, a0.w);
    }

    float4 s;
    s.x = a0.x + a1.x; s.y = a0.y + a1.y; s.z = a0.z + a1.z; s.w = a0.w + a1.w;
    s_red[tid] = s;
    __syncthreads();

    if (tid < 80) {
        float4 r0 = s_red[tid], r1 = s_red[tid + 80];
        float4 r2 = s_red[tid + 160], r3 = s_red[tid + 240];
        float4 o;
        o.x = (r0.x + r1.x) + (r2.x + r3.x);
        o.y = (r0.y + r1.y) + (r2.y + r3.y);
        o.z = (r0.z + r1.z) + (r2.z + r3.z);
        o.w = (r0.w + r1.w) + (r2.w + r3.w);
        s_red2[tid] = o;
    }
    __syncthreads();

    if (tid < 20) {
        float4 r0 = s_red2[tid], r1 = s_red2[tid + 20];
        float4 r2 = s_red2[tid + 40], r3 = s_red2[tid + 60];
        float4 o;
        o.x = (r0.x + r1.x) + (r2.x + r3.x);
        o.y = (r0.y + r1.y) + (r2.y + r3.y);
        o.z = (r0.z + r1.z) + (r2.z + r3.z);
        o.w = (r0.w + r1.w) + (r2.w + r3.w);
        ((float4*)out_w)[(size_t)b * 20 + tid] = o;
    }
}

extern "C" void kernel_launch(void* const* d_in, const int* in_sizes, int n_in,
                              void* d_out, int out_size) {
    const float* X          = (const float*)d_in[0];   // [B, D]
    const float* prev_kappa = (const float*)d_in[1];   // [B, K]
    const float* oh         = (const float*)d_in[2];   // [B, L, V]
    const int*   seqlens    = (const int*)  d_in[3];   // [B]
    const float* W          = (const float*)d_in[4];   // [D, 3K]
    const float* bias       = (const float*)d_in[5];   // [3K]
    const float* ks         = (const float*)d_in[6];   // scalar

    float* out       = (float*)d_out;
    float* out_w     = out;              // [B, V] first (reference returns (w, kappa))
    float* out_kappa = out + BQ * VV;    // [B, K] second

    gemm_act_kernel<<<128, 256>>>(X, W, bias, prev_kappa, ks, out_kappa);
    phi_w_kernel<<<BQ, 320>>>(oh, seqlens, out_w);
}

// round 5
// speedup vs baseline: 2.3030x; 1.9898x over previous
#include <cuda_runtime.h>

// Problem constants (from reference): B=4096, D=512, K=10, L=256, V=80
#define BQ 4096
#define DD 512
#define KK 10
#define LL 256
#define VV 80

// Scratch for alpha[0:10], beta[10:20], kappa[20:30] per batch row.
__device__ float g_abk[BQ * 30];

// exp(e) for e in [-50, 0], FMA-pipe only (no MUFU).
__device__ __forceinline__ float fast_exp_neg(float e) {
    float t = e * 1.44269504088896341f;
    int i = __float2int_rd(t);
    float f = t - (float)i;
    float p = 1.5403530393381610e-4f;
    p = fmaf(p, f, 1.3333558146428443e-3f);
    p = fmaf(p, f, 9.6181291076284772e-3f);
    p = fmaf(p, f, 5.5504108664821580e-2f);
    p = fmaf(p, f, 2.4022650695910071e-1f);
    p = fmaf(p, f, 6.9314718055994531e-1f);
    p = fmaf(p, f, 1.0f);
    return p * __int_as_float((i + 127) << 23);
}

// Kernel A: raw = X@W + b, activations, write kappa to output + abk scratch.
// 128 blocks x 512 threads; block = 32 batch rows; warp w owns rows 2w..2w+1,
// lane = output column (lanes 30,31 idle).
__global__ __launch_bounds__(512) void gemm_act_kernel(
    const float* __restrict__ X, const float* __restrict__ W,
    const float* __restrict__ bias, const float* __restrict__ prev_kappa,
    const float* __restrict__ kappa_scale_p, float* __restrict__ out_kappa)
{
    __shared__ float4 Xs4[32 * 32];                   // 32 rows x 32 float4 = 16 KB
    __shared__ __align__(16) float Wsh[128 * 30 + 4]; // W tile + pad for lanes 30/31

    const int tid  = threadIdx.x;
    const int warp = tid >> 5;
    const int lane = tid & 31;
    const int b0   = blockIdx.x * 32;

    const float4* X4 = (const float4*)X;
    const float4* W4 = (const float4*)W;   // W [512,30] row-major -> 3840 float4 linear

    float acc[2] = {0.f, 0.f};

    for (int t = 0; t < 4; ++t) {
        __syncthreads();
        for (int i = tid; i < 960; i += 512)
            ((float4*)Wsh)[i] = W4[t * 960 + i];
        for (int i = tid; i < 1024; i += 512) {
            int r = i >> 5, c = i & 31;
            Xs4[i] = X4[(size_t)(b0 + r) * 128 + t * 32 + c];
        }
        __syncthreads();

        const float4* xr0 = &Xs4[(warp * 2 + 0) * 32];
        const float4* xr1 = &Xs4[(warp * 2 + 1) * 32];

        #pragma unroll 8
        for (int c = 0; c < 32; ++c) {
            float w0 = Wsh[(4 * c + 0) * 30 + lane];
            float w1 = Wsh[(4 * c + 1) * 30 + lane];
            float w2 = Wsh[(4 * c + 2) * 30 + lane];
            float w3 = Wsh[(4 * c + 3) * 30 + lane];
            float4 x0 = xr0[c], x1 = xr1[c];
            acc[0] = fmaf(x0.x, w0, fmaf(x0.y, w1, fmaf(x0.z, w2, fmaf(x0.w, w3, acc[0]))));
            acc[1] = fmaf(x1.x, w0, fmaf(x1.y, w1, fmaf(x1.z, w2, fmaf(x1.w, w3, acc[1]))));
        }
    }

    if (lane < 30) {
        const float bj = bias[lane];
        const float ks = *kappa_scale_p;
        #pragma unroll
        for (int rr = 0; rr < 2; ++rr) {
            int b = b0 + warp * 2 + rr;
            float raw = acc[rr] + bj;
            float val;
            if (lane < 20) {
                val = __expf(fminf(fmaxf(raw, -8.f), 8.f));
            } else {
                float dk = __expf(fminf(fmaxf(raw + ks, -8.f), 5.f));
                val = prev_kappa[b * KK + (lane - 20)] + dk;
                out_kappa[b * KK + (lane - 20)] = val;
            }
            g_abk[b * 30 + lane] = val;
        }
    }
}

// Kernel B: per batch row: phi[l] for l<seqlen, then truncate at the last l where
// phi[l] > 1e-7*max(phi) (Gaussian windows are concentrated at small l since
// kappa ~ U[0,1] + lognormal), then w[v] = sum_{l<l_hi} phi[l]*oh[b,l,v].
// 4096 blocks x 320 threads; 16 l-groups x 20 float4 lanes, fully coalesced.
__global__ __launch_bounds__(320) void phi_w_kernel(
    const float* __restrict__ oh, const int* __restrict__ seqlens,
    float* __restrict__ out_w)
{
    __shared__ float  s_abk[30];
    __shared__ float  s_phi[LL];
    __shared__ float  s_wmax[10];
    __shared__ int    s_wlhi[10];
    __shared__ int    s_lhi;
    __shared__ float4 s_red[320];
    __shared__ float4 s_red2[80];
    const int b    = blockIdx.x;
    const int tid  = threadIdx.x;
    const int warp = tid >> 5;
    const int lane = tid & 31;

    if (tid < 30) s_abk[tid] = g_abk[b * 30 + tid];
    __syncthreads();

    const int seqlen = seqlens[b];

    float p = 0.f;
    if (tid < LL && tid < seqlen) {
        float u = (float)(tid + 1);
        float s = 0.f;
        #pragma unroll
        for (int k = 0; k < KK; ++k) {
            float al = s_abk[k];
            float be = s_abk[10 + k];
            float ka = s_abk[20 + k];
            float dv = ka - u;
            float e  = fmaxf(-be * dv * dv, -50.f);
            s = fmaf(al, fast_exp_neg(e), s);
        }
        s_phi[tid] = s;
        p = s;
    }

    // max(phi) over the block (warps 8,9 contribute p=0)
    float m = p;
    #pragma unroll
    for (int off = 16; off > 0; off >>= 1)
        m = fmaxf(m, __shfl_xor_sync(0xffffffffu, m, off));
    if (lane == 0) s_wmax[warp] = m;
    __syncthreads();
    if (tid == 0) {
        float mm = s_wmax[0];
        #pragma unroll
        for (int i = 1; i < 10; ++i) mm = fmaxf(mm, s_wmax[i]);
        s_wmax[0] = mm;
    }
    __syncthreads();
    const float theta = s_wmax[0] * 1e-7f;

    // last l with phi[l] > theta
    unsigned bal = __ballot_sync(0xffffffffu, p > theta);
    int wl = bal ? (warp * 32 + 31 - __clz(bal)) : -1;
    if (lane == 0) s_wlhi[warp] = wl;
    __syncthreads();
    if (tid == 0) {
        int h = -1;
        #pragma unroll
        for (int i = 0; i < 10; ++i) h = max(h, s_wlhi[i]);
        s_lhi = h + 1;
    }
    __syncthreads();
    const int l_hi = s_lhi;   // <= seqlen

    const int g  = tid / 20;         // l-group 0..15
    const int v4 = tid - g * 20;     // float4 lane 0..19
    const float4* row = (const float4*)oh + (size_t)b * (LL * VV / 4) + v4;

    float4 a0 = make_float4(0.f, 0.f, 0.f, 0.f);
    float4 a1 = a0;
    int l = g;
    for (; l + 48 < l_hi; l += 64) {
        float4 x0 = row[(size_t)(l)      * 20];
        float4 x1 = row[(size_t)(l + 16) * 20];
        float4 x2 = row[(size_t)(l + 32) * 20];
        float4 x3 = row[(size_t)(l + 48) * 20];
        float p0 = s_phi[l], p1 = s_phi[l + 16], p2 = s_phi[l + 32], p3 = s_phi[l + 48];
        a0.x = fmaf(p0, x0.x, a0.x); a0.y = fmaf(p0, x0.y, a0.y);
        a0.z = fmaf(p0, x0.z, a0.z); a0.w = fmaf(p0, x0.w, a0.w);
        a1.x = fmaf(p1, x1.x, a1.x); a1.y = fmaf(p1, x1.y, a1.y);
        a1.z = fmaf(p1, x1.z, a1.z); a1.w = fmaf(p1, x1.w, a1.w);
        a0.x = fmaf(p2, x2.x, a0.x); a0.y = fmaf(p2, x2.y, a0.y);
        a0.z = fmaf(p2, x2.z, a0.z); a0.w = fmaf(p2, x2.w, a0.w);
        a1.x = fmaf(p3, x3.x, a1.x); a1.y = fmaf(p3, x3.y, a1.y);
        a1.z = fmaf(p3, x3.z, a1.z); a1.w = fmaf(p3, x3.w, a1.w);
    }
    for (; l < l_hi; l += 16) {
        float4 x = row[(size_t)l * 20];
        float pp = s_phi[l];
        a0.x = fmaf(pp, x.x, a0.x); a0.y = fmaf(pp, x.y, a0.y);
        a0.z = fmaf(pp, x.z, a0.z); a0.w = fmaf(pp, x.w, a0.w);
    }

    float4 s;
    s.x = a0.x + a1.x; s.y = a0.y + a1.y; s.z = a0.z + a1.z; s.w = a0.w + a1.w;
    s_red[tid] = s;
    __syncthreads();

    if (tid < 80) {
        float4 r0 = s_red[tid], r1 = s_red[tid + 80];
        float4 r2 = s_red[tid + 160], r3 = s_red[tid + 240];
        float4 o;
        o.x = (r0.x + r1.x) + (r2.x + r3.x);
        o.y = (r0.y + r1.y) + (r2.y + r3.y);
        o.z = (r0.z + r1.z) + (r2.z + r3.z);
        o.w = (r0.w + r1.w) + (r2.w + r3.w);
        s_red2[tid] = o;
    }
    __syncthreads();

    if (tid < 20) {
        float4 r0 = s_red2[tid], r1 = s_red2[tid + 20];
        float4 r2 = s_red2[tid + 40], r3 = s_red2[tid + 60];
        float4 o;
        o.x = (r0.x + r1.x) + (r2.x + r3.x);
        o.y = (r0.y + r1.y) + (r2.y + r3.y);
        o.z = (r0.z + r1.z) + (r2.z + r3.z);
        o.w = (r0.w + r1.w) + (r2.w + r3.w);
        ((float4*)out_w)[(size_t)b * 20 + tid] = o;
    }
}

extern "C" void kernel_launch(void* const* d_in, const int* in_sizes, int n_in,
                              void* d_out, int out_size) {
    const float* X          = (const float*)d_in[0];   // [B, D]
    const float* prev_kappa = (const float*)d_in[1];   // [B, K]
    const float* oh         = (const float*)d_in[2];   // [B, L, V]
    const int*   seqlens    = (const int*)  d_in[3];   // [B]
    const float* W          = (const float*)d_in[4];   // [D, 3K]
    const float* bias       = (const float*)d_in[5];   // [3K]
    const float* ks         = (const float*)d_in[6];   // scalar

    float* out       = (float*)d_out;
    float* out_w     = out;              // [B, V]
    float* out_kappa = out + BQ * VV;    // [B, K]

    gemm_act_kernel<<<128, 512>>>(X, W, bias, prev_kappa, ks, out_kappa);
    phi_w_kernel<<<BQ, 320>>>(oh, seqlens, out_w);
}

// round 6
// speedup vs baseline: 2.6316x; 1.1427x over previous
#include <cuda_runtime.h>

// Problem constants (from reference): B=4096, D=512, K=10, L=256, V=80
#define BQ 4096
#define DD 512
#define KK 10
#define LL 256
#define VV 80

// Scratch for alpha[0:10], beta[10:20], kappa[20:30] per batch row.
__device__ float g_abk[BQ * 30];

// exp(e) for e in [-50, 0], FMA-pipe only (no MUFU).
__device__ __forceinline__ float fast_exp_neg(float e) {
    float t = e * 1.44269504088896341f;
    int i = __float2int_rd(t);
    float f = t - (float)i;
    float p = 1.5403530393381610e-4f;
    p = fmaf(p, f, 1.3333558146428443e-3f);
    p = fmaf(p, f, 9.6181291076284772e-3f);
    p = fmaf(p, f, 5.5504108664821580e-2f);
    p = fmaf(p, f, 2.4022650695910071e-1f);
    p = fmaf(p, f, 6.9314718055994531e-1f);
    p = fmaf(p, f, 1.0f);
    return p * __int_as_float((i + 127) << 23);
}

// Kernel A: raw = X@W + b, activations, write kappa to output + abk scratch.
// 256 blocks x 256 threads; block = 16 batch rows (2 blocks/SM so tile-load
// latency of one block hides under the other's FMA stream).
// Warp w (0..7) owns rows 2w, 2w+1; lane = output column (lanes 30,31 idle).
__global__ __launch_bounds__(256) void gemm_act_kernel(
    const float* __restrict__ X, const float* __restrict__ W,
    const float* __restrict__ bias, const float* __restrict__ prev_kappa,
    const float* __restrict__ kappa_scale_p, float* __restrict__ out_kappa)
{
    __shared__ float4 Xs4[16 * 32];                   // 16 rows x 32 float4 = 8 KB
    __shared__ __align__(16) float Wsh[128 * 30 + 4]; // W tile + pad for lanes 30/31

    const int tid  = threadIdx.x;
    const int warp = tid >> 5;
    const int lane = tid & 31;
    const int b0   = blockIdx.x * 16;

    const float4* X4 = (const float4*)X;
    const float4* W4 = (const float4*)W;   // W [512,30] row-major -> 3840 float4 linear

    float acc[2] = {0.f, 0.f};

    for (int t = 0; t < 4; ++t) {
        __syncthreads();
        for (int i = tid; i < 960; i += 256)
            ((float4*)Wsh)[i] = W4[t * 960 + i];
        for (int i = tid; i < 512; i += 256) {
            int r = i >> 5, c = i & 31;
            Xs4[i] = X4[(size_t)(b0 + r) * 128 + t * 32 + c];
        }
        __syncthreads();

        const float4* xr0 = &Xs4[(warp * 2 + 0) * 32];
        const float4* xr1 = &Xs4[(warp * 2 + 1) * 32];

        #pragma unroll 8
        for (int c = 0; c < 32; ++c) {
            float w0 = Wsh[(4 * c + 0) * 30 + lane];
            float w1 = Wsh[(4 * c + 1) * 30 + lane];
            float w2 = Wsh[(4 * c + 2) * 30 + lane];
            float w3 = Wsh[(4 * c + 3) * 30 + lane];
            float4 x0 = xr0[c], x1 = xr1[c];
            acc[0] = fmaf(x0.x, w0, fmaf(x0.y, w1, fmaf(x0.z, w2, fmaf(x0.w, w3, acc[0]))));
            acc[1] = fmaf(x1.x, w0, fmaf(x1.y, w1, fmaf(x1.z, w2, fmaf(x1.w, w3, acc[1]))));
        }
    }

    if (lane < 30) {
        const float bj = bias[lane];
        const float ks = *kappa_scale_p;
        #pragma unroll
        for (int rr = 0; rr < 2; ++rr) {
            int b = b0 + warp * 2 + rr;
            float raw = acc[rr] + bj;
            float val;
            if (lane < 20) {
                val = __expf(fminf(fmaxf(raw, -8.f), 8.f));
            } else {
                float dk = __expf(fminf(fmaxf(raw + ks, -8.f), 5.f));
                val = prev_kappa[b * KK + (lane - 20)] + dk;
                out_kappa[b * KK + (lane - 20)] = val;
            }
            g_abk[b * 30 + lane] = val;
        }
    }
}

// Kernel B: 1024 blocks x 320 threads, 4 batch rows per block (80 threads/row:
// 4 l-groups x 20 float4 lanes). Analytic truncation: per row, 10 threads
// compute each mixture component's peak p_k at the nearest integer position
// (lower bound on max phi), theta = 1e-8 * max_k p_k, then the component's
// reach l_k = kappa_k + sqrt(ln(alpha_k/theta)/beta_k); l_hi = max_k l_k.
// phi is computed only for l < l_hi (~16 on average). The first 8 one-hot
// chunks per row are prefetched before the param phase so the global-load
// latency hides under the entire param/phi critical path.
__global__ __launch_bounds__(320) void phi_w_kernel(
    const float* __restrict__ oh, const int* __restrict__ seqlens,
    float* __restrict__ out_w)
{
    __shared__ float  s_abk[4][30];
    __shared__ float  s_pk[4][10];
    __shared__ int    s_lhi[4];
    __shared__ float  s_phi[4][LL];
    __shared__ float4 s_red[320];

    const int tid = threadIdx.x;
    const int r   = tid / 80;          // row slot 0..3
    const int rt  = tid - r * 80;      // 0..79 within row
    const int g   = rt / 20;           // l-group 0..3
    const int v4  = rt - g * 20;       // float4 lane 0..19
    const int b   = blockIdx.x * 4 + r;

    const int seqlen = seqlens[b];
    const float4* row = (const float4*)oh + (size_t)b * (LL * (VV / 4)) + v4;

    // Prefetch first two chunks (l = g, g+4) — covers typical l_hi while the
    // parameter chain resolves.
    float4 x0 = make_float4(0.f, 0.f, 0.f, 0.f);
    float4 x1 = x0;
    if (g < seqlen)     x0 = row[(size_t)(g)     * 20];
    if (g + 4 < seqlen) x1 = row[(size_t)(g + 4) * 20];

    // Phase 1: params + per-component peak.
    float al = 0.f, be = 1.f, ka = 0.f;
    if (rt < 10) {
        al = g_abk[b * 30 + rt];
        be = g_abk[b * 30 + 10 + rt];
        ka = g_abk[b * 30 + 20 + rt];
        s_abk[r][rt]      = al;
        s_abk[r][10 + rt] = be;
        s_abk[r][20 + rt] = ka;
        float ustar = fminf(fmaxf(rintf(ka), 1.f), (float)seqlen);
        float d  = ka - ustar;
        float pk = al * __expf(fmaxf(-be * d * d, -87.f));
        s_pk[r][rt] = pk;
        if (rt == 0) s_lhi[r] = 0;
    }
    __syncthreads();

    // Phase 2: threshold + per-component reach.
    if (rt < 10) {
        float mm = s_pk[r][0];
        #pragma unroll
        for (int i = 1; i < 10; ++i) mm = fmaxf(mm, s_pk[r][i]);
        float theta = mm * 1e-8f;
        float lnr = __logf(al) - __logf(theta);      // theta==0 -> +inf -> full
        float lk  = ka + sqrtf(fmaxf(lnr, 0.f) / be);
        lk = fminf(lk, 256.f);
        atomicMax(&s_lhi[r], (int)ceilf(lk));
    }
    __syncthreads();

    const int l_use = min(s_lhi[r], seqlen);

    // Phase 3: phi only where it matters.
    for (int l = rt; l < l_use; l += 80) {
        float u = (float)(l + 1);
        float s = 0.f;
        #pragma unroll
        for (int k = 0; k < KK; ++k) {
            float a = s_abk[r][k];
            float bb = s_abk[r][10 + k];
            float kk = s_abk[r][20 + k];
            float dv = kk - u;
            float e  = fmaxf(-bb * dv * dv, -50.f);
            s = fmaf(a, fast_exp_neg(e), s);
        }
        s_phi[r][l] = s;
    }
    __syncthreads();

    // Phase 4: accumulate (prefetched chunks first, then residual loop).
    float4 a0 = make_float4(0.f, 0.f, 0.f, 0.f);
    if (g < l_use) {
        float p = s_phi[r][g];
        a0.x = p * x0.x; a0.y = p * x0.y; a0.z = p * x0.z; a0.w = p * x0.w;
    }
    if (g + 4 < l_use) {
        float p = s_phi[r][g + 4];
        a0.x = fmaf(p, x1.x, a0.x); a0.y = fmaf(p, x1.y, a0.y);
        a0.z = fmaf(p, x1.z, a0.z); a0.w = fmaf(p, x1.w, a0.w);
    }
    {
        int l = g + 8;
        for (; l + 4 < l_use; l += 8) {
            float4 y0 = row[(size_t)(l)     * 20];
            float4 y1 = row[(size_t)(l + 4) * 20];
            float p0 = s_phi[r][l], p1 = s_phi[r][l + 4];
            a0.x = fmaf(p0, y0.x, a0.x); a0.y = fmaf(p0, y0.y, a0.y);
            a0.z = fmaf(p0, y0.z, a0.z); a0.w = fmaf(p0, y0.w, a0.w);
            a0.x = fmaf(p1, y1.x, a0.x); a0.y = fmaf(p1, y1.y, a0.y);
            a0.z = fmaf(p1, y1.z, a0.z); a0.w = fmaf(p1, y1.w, a0.w);
        }
        for (; l < l_use; l += 4) {
            float4 y = row[(size_t)l * 20];
            float p = s_phi[r][l];
            a0.x = fmaf(p, y.x, a0.x); a0.y = fmaf(p, y.y, a0.y);
            a0.z = fmaf(p, y.z, a0.z); a0.w = fmaf(p, y.w, a0.w);
        }
    }
    s_red[tid] = a0;
    __syncthreads();

    // Phase 5: reduce 4 groups per row, store.
    if (rt < 20) {
        float4 r0 = s_red[r * 80 + rt];
        float4 r1 = s_red[r * 80 + rt + 20];
        float4 r2 = s_red[r * 80 + rt + 40];
        float4 r3 = s_red[r * 80 + rt + 60];
        float4 o;
        o.x = (r0.x + r1.x) + (r2.x + r3.x);
        o.y = (r0.y + r1.y) + (r2.y + r3.y);
        o.z = (r0.z + r1.z) + (r2.z + r3.z);
        o.w = (r0.w + r1.w) + (r2.w + r3.w);
        ((float4*)out_w)[(size_t)b * 20 + rt] = o;
    }
}

extern "C" void kernel_launch(void* const* d_in, const int* in_sizes, int n_in,
                              void* d_out, int out_size) {
    const float* X          = (const float*)d_in[0];   // [B, D]
    const float* prev_kappa = (const float*)d_in[1];   // [B, K]
    const float* oh         = (const float*)d_in[2];   // [B, L, V]
    const int*   seqlens    = (const int*)  d_in[3];   // [B]
    const float* W          = (const float*)d_in[4];   // [D, 3K]
    const float* bias       = (const float*)d_in[5];   // [3K]
    const float* ks         = (const float*)d_in[6];   // scalar

    float* out       = (float*)d_out;
    float* out_w     = out;              // [B, V]
    float* out_kappa = out + BQ * VV;    // [B, K]

    gemm_act_kernel<<<256, 256>>>(X, W, bias, prev_kappa, ks, out_kappa);
    phi_w_kernel<<<BQ / 4, 320>>>(oh, seqlens, out_w);
}

// round 7
// speedup vs baseline: 2.6564x; 1.0094x over previous
#include <cuda_runtime.h>

// Problem constants (from reference): B=4096, D=512, K=10, L=256, V=80
#define BQ 4096
#define DD 512
#define KK 10
#define LL 256
#define VV 80

// Scratch for alpha[0:10], beta[10:20], kappa[20:30] per batch row.
__device__ float g_abk[BQ * 30];

// exp(e) for e in [-50, 0], FMA-pipe only (no MUFU).
__device__ __forceinline__ float fast_exp_neg(float e) {
    float t = e * 1.44269504088896341f;
    int i = __float2int_rd(t);
    float f = t - (float)i;
    float p = 1.5403530393381610e-4f;
    p = fmaf(p, f, 1.3333558146428443e-3f);
    p = fmaf(p, f, 9.6181291076284772e-3f);
    p = fmaf(p, f, 5.5504108664821580e-2f);
    p = fmaf(p, f, 2.4022650695910071e-1f);
    p = fmaf(p, f, 6.9314718055994531e-1f);
    p = fmaf(p, f, 1.0f);
    return p * __int_as_float((i + 127) << 23);
}

// Kernel A (unchanged from R6): raw = X@W + b, activations, kappa out + abk scratch.
// 256 blocks x 256 threads; block = 16 batch rows; warp w owns rows 2w,2w+1.
__global__ __launch_bounds__(256) void gemm_act_kernel(
    const float* __restrict__ X, const float* __restrict__ W,
    const float* __restrict__ bias, const float* __restrict__ prev_kappa,
    const float* __restrict__ kappa_scale_p, float* __restrict__ out_kappa)
{
    __shared__ float4 Xs4[16 * 32];
    __shared__ __align__(16) float Wsh[128 * 30 + 4];

    const int tid  = threadIdx.x;
    const int warp = tid >> 5;
    const int lane = tid & 31;
    const int b0   = blockIdx.x * 16;

    const float4* X4 = (const float4*)X;
    const float4* W4 = (const float4*)W;

    float acc[2] = {0.f, 0.f};

    for (int t = 0; t < 4; ++t) {
        __syncthreads();
        for (int i = tid; i < 960; i += 256)
            ((float4*)Wsh)[i] = W4[t * 960 + i];
        for (int i = tid; i < 512; i += 256) {
            int r = i >> 5, c = i & 31;
            Xs4[i] = X4[(size_t)(b0 + r) * 128 + t * 32 + c];
        }
        __syncthreads();

        const float4* xr0 = &Xs4[(warp * 2 + 0) * 32];
        const float4* xr1 = &Xs4[(warp * 2 + 1) * 32];

        #pragma unroll 8
        for (int c = 0; c < 32; ++c) {
            float w0 = Wsh[(4 * c + 0) * 30 + lane];
            float w1 = Wsh[(4 * c + 1) * 30 + lane];
            float w2 = Wsh[(4 * c + 2) * 30 + lane];
            float w3 = Wsh[(4 * c + 3) * 30 + lane];
            float4 x0 = xr0[c], x1 = xr1[c];
            acc[0] = fmaf(x0.x, w0, fmaf(x0.y, w1, fmaf(x0.z, w2, fmaf(x0.w, w3, acc[0]))));
            acc[1] = fmaf(x1.x, w0, fmaf(x1.y, w1, fmaf(x1.z, w2, fmaf(x1.w, w3, acc[1]))));
        }
    }

    if (lane < 30) {
        const float bj = bias[lane];
        const float ks = *kappa_scale_p;
        #pragma unroll
        for (int rr = 0; rr < 2; ++rr) {
            int b = b0 + warp * 2 + rr;
            float raw = acc[rr] + bj;
            float val;
            if (lane < 20) {
                val = __expf(fminf(fmaxf(raw, -8.f), 8.f));
            } else {
                float dk = __expf(fminf(fmaxf(raw + ks, -8.f), 5.f));
                val = prev_kappa[b * KK + (lane - 20)] + dk;
                out_kappa[b * KK + (lane - 20)] = val;
            }
            g_abk[b * 30 + lane] = val;
        }
    }
}

// Kernel B: warp-per-row, no block barriers. 512 blocks x 256 threads (8 warps).
// Lane owns vocab positions {lane, lane+32, lane+64(<80)} -> no cross-thread
// reduction; direct coalesced STG. Analytic truncation l_hi via warp shuffles.
// First 8 one-hot rows prefetched in the same load front as the params.
__global__ __launch_bounds__(256) void phi_w_kernel(
    const float* __restrict__ oh, const int* __restrict__ seqlens,
    float* __restrict__ out_w)
{
    __shared__ float s_phi[8][LL];
    __shared__ float s_abk[8][30];

    const int wrow = threadIdx.x >> 5;
    const int lane = threadIdx.x & 31;
    const int b    = blockIdx.x * 8 + wrow;

    const float* row = oh + (size_t)b * (LL * VV);

    // ---- Front batch of independent loads: params + seqlen + 8 l prefetch ----
    float al = 0.f, be = 1.f, ka = 0.f;
    if (lane < 10) {
        al = g_abk[b * 30 + lane];
        be = g_abk[b * 30 + 10 + lane];
        ka = g_abk[b * 30 + 20 + lane];
    }
    const int seqlen = seqlens[b];

    float pf0[8], pf1[8], pf2[8];
    #pragma unroll
    for (int l = 0; l < 8; ++l) {   // unconditional: oh rows are dense/valid
        pf0[l] = row[l * VV + lane];
        pf1[l] = row[l * VV + 32 + lane];
        pf2[l] = (lane < 16) ? row[l * VV + 64 + lane] : 0.f;
    }

    // ---- Per-component peak at nearest integer (lower bound on max phi) ----
    float pk = 0.f;
    if (lane < 10) {
        float ustar = fminf(fmaxf(rintf(ka), 1.f), (float)seqlen);
        float d = ka - ustar;
        pk = al * __expf(fmaxf(-be * d * d, -87.f));
        s_abk[wrow][lane]      = al;
        s_abk[wrow][10 + lane] = be;
        s_abk[wrow][20 + lane] = ka;
    }
    float pm = pk;
    #pragma unroll
    for (int off = 16; off > 0; off >>= 1)
        pm = fmaxf(pm, __shfl_xor_sync(0xffffffffu, pm, off));
    const float theta = pm * 1e-8f;

    // ---- Per-component reach; warp-max -> l_hi ----
    float lk = 0.f;
    if (lane < 10) {
        float lnr = __logf(al) - __logf(theta);   // theta==0 -> +inf -> full length
        lk = ka + sqrtf(fmaxf(lnr, 0.f) / be);
        lk = fminf(lk, 256.f);
    }
    #pragma unroll
    for (int off = 16; off > 0; off >>= 1)
        lk = fmaxf(lk, __shfl_xor_sync(0xffffffffu, lk, off));
    const int l_hi = min((int)ceilf(lk), seqlen);

    // ---- phi[l] for l < l_hi (warp-strided), warp-sync only ----
    __syncwarp();
    for (int l = lane; l < l_hi; l += 32) {
        float u = (float)(l + 1);
        float s = 0.f;
        #pragma unroll
        for (int k = 0; k < KK; ++k) {
            float a  = s_abk[wrow][k];
            float bb = s_abk[wrow][10 + k];
            float kk = s_abk[wrow][20 + k];
            float dv = kk - u;
            float e  = fmaxf(-bb * dv * dv, -50.f);
            s = fmaf(a, fast_exp_neg(e), s);
        }
        s_phi[wrow][l] = s;
    }
    __syncwarp();

    // ---- Accumulate: prefetched chunk first, then pipelined residual ----
    float a0 = 0.f, a1 = 0.f, a2 = 0.f;
    const int lim = min(l_hi, 8);
    #pragma unroll
    for (int l = 0; l < 8; ++l) {
        if (l < lim) {
            float p = s_phi[wrow][l];
            a0 = fmaf(p, pf0[l], a0);
            a1 = fmaf(p, pf1[l], a1);
            a2 = fmaf(p, pf2[l], a2);
        }
    }
    int l = 8;
    for (; l + 3 < l_hi; l += 4) {
        float x00 = row[(l + 0) * VV + lane];
        float x01 = row[(l + 0) * VV + 32 + lane];
        float x02 = (lane < 16) ? row[(l + 0) * VV + 64 + lane] : 0.f;
        float x10 = row[(l + 1) * VV + lane];
        float x11 = row[(l + 1) * VV + 32 + lane];
        float x12 = (lane < 16) ? row[(l + 1) * VV + 64 + lane] : 0.f;
        float x20 = row[(l + 2) * VV + lane];
        float x21 = row[(l + 2) * VV + 32 + lane];
        float x22 = (lane < 16) ? row[(l + 2) * VV + 64 + lane] : 0.f;
        float x30 = row[(l + 3) * VV + lane];
        float x31 = row[(l + 3) * VV + 32 + lane];
        float x32 = (lane < 16) ? row[(l + 3) * VV + 64 + lane] : 0.f;
        float p0 = s_phi[wrow][l + 0];
        float p1 = s_phi[wrow][l + 1];
        float p2 = s_phi[wrow][l + 2];
        float p3 = s_phi[wrow][l + 3];
        a0 = fmaf(p0, x00, a0); a1 = fmaf(p0, x01, a1); a2 = fmaf(p0, x02, a2);
        a0 = fmaf(p1, x10, a0); a1 = fmaf(p1, x11, a1); a2 = fmaf(p1, x12, a2);
        a0 = fmaf(p2, x20, a0); a1 = fmaf(p2, x21, a1); a2 = fmaf(p2, x22, a2);
        a0 = fmaf(p3, x30, a0); a1 = fmaf(p3, x31, a1); a2 = fmaf(p3, x32, a2);
    }
    for (; l < l_hi; ++l) {
        float p = s_phi[wrow][l];
        a0 = fmaf(p, row[l * VV + lane], a0);
        a1 = fmaf(p, row[l * VV + 32 + lane], a1);
        if (lane < 16) a2 = fmaf(p, row[l * VV + 64 + lane], a2);
    }

    out_w[(size_t)b * VV + lane]      = a0;
    out_w[(size_t)b * VV + 32 + lane] = a1;
    if (lane < 16)
        out_w[(size_t)b * VV + 64 + lane] = a2;
}

extern "C" void kernel_launch(void* const* d_in, const int* in_sizes, int n_in,
                              void* d_out, int out_size) {
    const float* X          = (const float*)d_in[0];   // [B, D]
    const float* prev_kappa = (const float*)d_in[1];   // [B, K]
    const float* oh         = (const float*)d_in[2];   // [B, L, V]
    const int*   seqlens    = (const int*)  d_in[3];   // [B]
    const float* W          = (const float*)d_in[4];   // [D, 3K]
    const float* bias       = (const float*)d_in[5];   // [3K]
    const float* ks         = (const float*)d_in[6];   // scalar

    float* out       = (float*)d_out;
    float* out_w     = out;              // [B, V]
    float* out_kappa = out + BQ * VV;    // [B, K]

    gemm_act_kernel<<<256, 256>>>(X, W, bias, prev_kappa, ks, out_kappa);
    phi_w_kernel<<<BQ / 8, 256>>>(oh, seqlens, out_w);
}